// round 4
// baseline (speedup 1.0000x reference)
#include <cuda_runtime.h>
#include <cstdint>

#define BATCH 32768
#define DIM   512

// ---------------- scratch (device globals; no allocations allowed) ----------
__device__ float g_qkv [(size_t)3 * BATCH * 1536];  // [s][b][1536] (q|k|v)
__device__ float g_P   [(size_t)3 * BATCH * 512];   // attention output, [s][b][512]
__device__ float g_attn[(size_t)3 * BATCH * 512];   // attn_out (post residual), [s][b][512]
__device__ float g_gate[(size_t)BATCH * 3];         // softmax gates
__device__ float g_h   [(size_t)BATCH * 1024];      // MLP hidden
__device__ float g_fus [(size_t)BATCH * 512];       // pre-LN fused

// ---------------- tf32 helpers ----------------------------------------------
__device__ __forceinline__ float to_tf32(float x){
    uint32_t u; asm("cvt.rna.tf32.f32 %0, %1;" : "=r"(u) : "f"(x));
    return __uint_as_float(u);
}
__device__ __forceinline__ float4 to_tf32_4(float4 v){
    v.x = to_tf32(v.x); v.y = to_tf32(v.y); v.z = to_tf32(v.z); v.w = to_tf32(v.w);
    return v;
}
__device__ __forceinline__ void mma8(float c[4], const float a[4], const float b[2]){
    asm volatile(
        "mma.sync.aligned.m16n8k8.row.col.f32.tf32.tf32.f32 "
        "{%0,%1,%2,%3}, {%4,%5,%6,%7}, {%8,%9}, {%0,%1,%2,%3};\n"
        : "+f"(c[0]), "+f"(c[1]), "+f"(c[2]), "+f"(c[3])
        : "r"(__float_as_uint(a[0])), "r"(__float_as_uint(a[1])),
          "r"(__float_as_uint(a[2])), "r"(__float_as_uint(a[3])),
          "r"(__float_as_uint(b[0])), "r"(__float_as_uint(b[1])));
}

// ---------------- generic 128x128x16 tf32 GEMM:  C = A * W^T (+epilogue) -----
// MODE 0: QKV       A = stream z (x0/x1/x2), K=512,  N=1536 -> g_qkv[z]
// MODE 1: out-proj  A = g_P (M=3B rows),     K=512,  N=512  -> g_attn (+bias+residual)
// MODE 2: MLP1      A = g_attn * gates,      K=1536, N=1024 -> g_h (SiLU(+bias))
// MODE 3: MLP2      A = g_h,                 K=1024, N=512  -> g_fus (+bias)
template<int MODE>
__global__ void __launch_bounds__(256)
gemm_kernel(const float* __restrict__ Wt, const float* __restrict__ bias,
            const float* __restrict__ x0, const float* __restrict__ x1,
            const float* __restrict__ x2)
{
    constexpr int KK = (MODE==0) ? 512  : (MODE==1) ? 512 : (MODE==2) ? 1536 : 1024;
    constexpr int KT = KK / 16;

    __shared__ float sA[2][128][20];
    __shared__ float sW[2][128][20];

    const int t    = threadIdx.x;
    const int lane = t & 31, warp = t >> 5;
    const int wm   = warp & 1;        // 2 warps along M (64 rows each)
    const int wn   = warp >> 1;       // 4 warps along N (32 cols each)
    const int gid  = lane >> 2, tig = lane & 3;

    const long long rowBase = (long long)blockIdx.y * 128;
    const int       colBase = blockIdx.x * 128;

    const int ldRow = t >> 2;         // 0..63
    const int ldCol = (t & 3) << 2;   // 0,4,8,12

    const float* Aptr = nullptr;
    if constexpr (MODE==0) Aptr = (blockIdx.z==0) ? x0 : (blockIdx.z==1) ? x1 : x2;
    if constexpr (MODE==1) Aptr = g_P;
    if constexpr (MODE==3) Aptr = g_h;

    float acc[4][4][4];
    #pragma unroll
    for (int i=0;i<4;i++)
        #pragma unroll
        for (int j=0;j<4;j++)
            #pragma unroll
            for (int l=0;l<4;l++) acc[i][j][l] = 0.f;

    float4 pa0, pa1, pw0, pw1;

    auto gload = [&](int k0){
        if constexpr (MODE==2){
            const int c = k0 + ldCol;
            const int s = c >> 9, cc = c & 511;
            const long long r0 = rowBase + ldRow, r1 = r0 + 64;
            const float gs0 = g_gate[r0*3 + s];
            const float gs1 = g_gate[r1*3 + s];
            float4 a = *(const float4*)(g_attn + ((long long)s*BATCH + r0)*512 + cc);
            float4 b = *(const float4*)(g_attn + ((long long)s*BATCH + r1)*512 + cc);
            a.x*=gs0; a.y*=gs0; a.z*=gs0; a.w*=gs0;
            b.x*=gs1; b.y*=gs1; b.z*=gs1; b.w*=gs1;
            pa0 = a; pa1 = b;
        } else {
            pa0 = *(const float4*)(Aptr + (rowBase + ldRow     )*KK + k0 + ldCol);
            pa1 = *(const float4*)(Aptr + (rowBase + ldRow + 64)*KK + k0 + ldCol);
        }
        pw0 = *(const float4*)(Wt + (long long)(colBase + ldRow     )*KK + k0 + ldCol);
        pw1 = *(const float4*)(Wt + (long long)(colBase + ldRow + 64)*KK + k0 + ldCol);
    };
    auto sstore = [&](int buf){
        *(float4*)&sA[buf][ldRow   ][ldCol] = to_tf32_4(pa0);
        *(float4*)&sA[buf][ldRow+64][ldCol] = to_tf32_4(pa1);
        *(float4*)&sW[buf][ldRow   ][ldCol] = to_tf32_4(pw0);
        *(float4*)&sW[buf][ldRow+64][ldCol] = to_tf32_4(pw1);
    };

    gload(0);
    sstore(0);
    __syncthreads();

    int buf = 0;
    for (int kt = 0; kt < KT; kt++){
        if (kt + 1 < KT) gload((kt+1)*16);
        #pragma unroll
        for (int kk = 0; kk < 16; kk += 8){
            float a[4][4];
            #pragma unroll
            for (int mi=0; mi<4; mi++){
                const int r = wm*64 + mi*16 + gid;
                a[mi][0] = sA[buf][r  ][kk+tig];
                a[mi][1] = sA[buf][r+8][kk+tig];
                a[mi][2] = sA[buf][r  ][kk+tig+4];
                a[mi][3] = sA[buf][r+8][kk+tig+4];
            }
            float b[4][2];
            #pragma unroll
            for (int ni=0; ni<4; ni++){
                const int cidx = wn*32 + ni*8 + gid;
                b[ni][0] = sW[buf][cidx][kk+tig];
                b[ni][1] = sW[buf][cidx][kk+tig+4];
            }
            #pragma unroll
            for (int mi=0; mi<4; mi++)
                #pragma unroll
                for (int ni=0; ni<4; ni++)
                    mma8(acc[mi][ni], a[mi], b[ni]);
        }
        if (kt + 1 < KT){
            sstore(buf ^ 1);
            __syncthreads();
            buf ^= 1;
        }
    }

    // epilogue
    #pragma unroll
    for (int mi=0; mi<4; mi++){
        const long long gr0 = rowBase + wm*64 + mi*16 + gid;
        const long long gr1 = gr0 + 8;
        #pragma unroll
        for (int ni=0; ni<4; ni++){
            const int gc = colBase + wn*32 + ni*8 + (tig<<1);
            const float bi0 = bias[gc], bi1 = bias[gc+1];
            float v00 = acc[mi][ni][0] + bi0;
            float v01 = acc[mi][ni][1] + bi1;
            float v10 = acc[mi][ni][2] + bi0;
            float v11 = acc[mi][ni][3] + bi1;
            if constexpr (MODE==0){
                float* C = g_qkv + (long long)blockIdx.z * BATCH * 1536;
                *(float2*)&C[gr0*1536 + gc] = make_float2(v00, v01);
                *(float2*)&C[gr1*1536 + gc] = make_float2(v10, v11);
            } else if constexpr (MODE==1){
                const int s = (int)(rowBase >> 15);           // 32768 rows per stream block
                const float* xs = (s==0) ? x0 : (s==1) ? x1 : x2;
                const long long b0 = gr0 & 32767, b1 = gr1 & 32767;
                v00 += xs[b0*512 + gc]; v01 += xs[b0*512 + gc + 1];
                v10 += xs[b1*512 + gc]; v11 += xs[b1*512 + gc + 1];
                *(float2*)&g_attn[gr0*512 + gc] = make_float2(v00, v01);
                *(float2*)&g_attn[gr1*512 + gc] = make_float2(v10, v11);
            } else if constexpr (MODE==2){
                v00 = v00 / (1.f + expf(-v00));
                v01 = v01 / (1.f + expf(-v01));
                v10 = v10 / (1.f + expf(-v10));
                v11 = v11 / (1.f + expf(-v11));
                *(float2*)&g_h[gr0*1024 + gc] = make_float2(v00, v01);
                *(float2*)&g_h[gr1*1024 + gc] = make_float2(v10, v11);
            } else {
                *(float2*)&g_fus[gr0*512 + gc] = make_float2(v00, v01);
                *(float2*)&g_fus[gr1*512 + gc] = make_float2(v10, v11);
            }
        }
    }
}

// ---------------- attention over S=3 streams: warp per (b, head) -------------
__global__ void __launch_bounds__(256) attn_kernel(){
    const int gw   = (blockIdx.x * 256 + threadIdx.x) >> 5;   // B*H warps
    const int lane = threadIdx.x & 31;
    const int b = gw >> 3;
    const int h = gw & 7;
    float q[3][2], k[3][2], v[3][2];
    #pragma unroll
    for (int s=0; s<3; s++){
        const long long p = ((long long)s*BATCH + b)*1536 + h*64 + lane;
        q[s][0] = g_qkv[p];        q[s][1] = g_qkv[p+32];
        k[s][0] = g_qkv[p+512];    k[s][1] = g_qkv[p+544];
        v[s][0] = g_qkv[p+1024];   v[s][1] = g_qkv[p+1056];
    }
    float sc[3][3];
    #pragma unroll
    for (int i=0;i<3;i++)
        #pragma unroll
        for (int j=0;j<3;j++){
            float d = q[i][0]*k[j][0] + q[i][1]*k[j][1];
            #pragma unroll
            for (int o=16;o>0;o>>=1) d += __shfl_xor_sync(0xffffffffu, d, o);
            sc[i][j] = d * 0.125f;                 // 1/sqrt(64)
        }
    #pragma unroll
    for (int i=0;i<3;i++){
        const float m  = fmaxf(sc[i][0], fmaxf(sc[i][1], sc[i][2]));
        float e0 = expf(sc[i][0]-m), e1 = expf(sc[i][1]-m), e2 = expf(sc[i][2]-m);
        const float inv = 1.f/(e0+e1+e2);
        e0*=inv; e1*=inv; e2*=inv;
        const float o0 = e0*v[0][0] + e1*v[1][0] + e2*v[2][0];
        const float o1 = e0*v[0][1] + e1*v[1][1] + e2*v[2][1];
        const long long p = ((long long)i*BATCH + b)*512 + h*64 + lane;
        g_P[p]    = o0;
        g_P[p+32] = o1;
    }
}

// ---------------- gate: softmax(attn_out_flat @ w_gate^T + b_gate) -----------
__global__ void __launch_bounds__(256) gate_kernel(const float* __restrict__ w_gate,
                                                   const float* __restrict__ b_gate){
    __shared__ float wg[3*1536];
    for (int i = threadIdx.x; i < 3*1536; i += 256) wg[i] = w_gate[i];
    __syncthreads();
    const int warp = threadIdx.x >> 5, lane = threadIdx.x & 31;
    const long long b = (long long)blockIdx.x*8 + warp;
    float a0=0.f, a1=0.f, a2=0.f;
    for (int j = lane; j < 1536; j += 32){
        const int s = j >> 9, d = j & 511;
        const float v = g_attn[((long long)s*BATCH + b)*512 + d];
        a0 += v*wg[j]; a1 += v*wg[1536+j]; a2 += v*wg[3072+j];
    }
    #pragma unroll
    for (int o=16;o>0;o>>=1){
        a0 += __shfl_xor_sync(~0u,a0,o);
        a1 += __shfl_xor_sync(~0u,a1,o);
        a2 += __shfl_xor_sync(~0u,a2,o);
    }
    if (lane == 0){
        a0 += b_gate[0]; a1 += b_gate[1]; a2 += b_gate[2];
        const float m = fmaxf(a0, fmaxf(a1, a2));
        float e0 = expf(a0-m), e1 = expf(a1-m), e2 = expf(a2-m);
        const float inv = 1.f/(e0+e1+e2);
        g_gate[b*3+0] = e0*inv;
        g_gate[b*3+1] = e1*inv;
        g_gate[b*3+2] = e2*inv;
    }
}

// ---------------- LayerNorm: warp per row ------------------------------------
__global__ void __launch_bounds__(256) ln_kernel(const float* __restrict__ gamma,
                                                 const float* __restrict__ beta,
                                                 float* __restrict__ out){
    const int warp = threadIdx.x >> 5, lane = threadIdx.x & 31;
    const long long row = (long long)blockIdx.x*8 + warp;
    const float* src = g_fus + row*512;
    float4 vals[4];
    float sum = 0.f;
    #pragma unroll
    for (int i=0;i<4;i++){
        vals[i] = *(const float4*)(src + i*128 + lane*4);
        sum += vals[i].x + vals[i].y + vals[i].z + vals[i].w;
    }
    #pragma unroll
    for (int o=16;o>0;o>>=1) sum += __shfl_xor_sync(~0u,sum,o);
    const float mu = sum * (1.f/512.f);
    float ss = 0.f;
    #pragma unroll
    for (int i=0;i<4;i++){
        float dx;
        dx = vals[i].x-mu; ss += dx*dx;
        dx = vals[i].y-mu; ss += dx*dx;
        dx = vals[i].z-mu; ss += dx*dx;
        dx = vals[i].w-mu; ss += dx*dx;
    }
    #pragma unroll
    for (int o=16;o>0;o>>=1) ss += __shfl_xor_sync(~0u,ss,o);
    const float rstd = rsqrtf(ss*(1.f/512.f) + 1e-5f);
    #pragma unroll
    for (int i=0;i<4;i++){
        const int c = i*128 + lane*4;
        const float4 g  = *(const float4*)(gamma + c);
        const float4 bt = *(const float4*)(beta  + c);
        float4 o;
        o.x = (vals[i].x-mu)*rstd*g.x + bt.x;
        o.y = (vals[i].y-mu)*rstd*g.y + bt.y;
        o.z = (vals[i].z-mu)*rstd*g.z + bt.z;
        o.w = (vals[i].w-mu)*rstd*g.w + bt.w;
        *(float4*)(out + row*512 + c) = o;
    }
}

// ---------------- launch -----------------------------------------------------
extern "C" void kernel_launch(void* const* d_in, const int* in_sizes, int n_in,
                              void* d_out, int out_size){
    (void)in_sizes; (void)n_in; (void)out_size;
    const float* kin    = (const float*)d_in[0];
    const float* col    = (const float*)d_in[1];
    const float* spin   = (const float*)d_in[2];
    const float* w_in   = (const float*)d_in[3];
    const float* b_in   = (const float*)d_in[4];
    const float* w_out  = (const float*)d_in[5];
    const float* b_out  = (const float*)d_in[6];
    const float* w_gate = (const float*)d_in[7];
    const float* b_gate = (const float*)d_in[8];
    const float* w1     = (const float*)d_in[9];
    const float* b1     = (const float*)d_in[10];
    const float* w2     = (const float*)d_in[11];
    const float* b2     = (const float*)d_in[12];
    const float* gamma  = (const float*)d_in[13];
    const float* beta   = (const float*)d_in[14];
    float* out = (float*)d_out;

    dim3 blk(256);
    gemm_kernel<0><<<dim3(12, 256, 3), blk>>>(w_in,  b_in,  kin, col, spin); // QKV
    attn_kernel  <<<32768, blk>>>();                                          // S=3 attention
    gemm_kernel<1><<<dim3(4, 768),    blk>>>(w_out, b_out, kin, col, spin);  // out-proj + residual
    gate_kernel  <<<4096, blk>>>(w_gate, b_gate);                             // stream gates
    gemm_kernel<2><<<dim3(8, 256),    blk>>>(w1,    b1,    nullptr, nullptr, nullptr); // MLP1 + SiLU
    gemm_kernel<3><<<dim3(4, 256),    blk>>>(w2,    b2,    nullptr, nullptr, nullptr); // MLP2
    ln_kernel    <<<4096, blk>>>(gamma, beta, out);                           // LayerNorm
}

// round 8
// speedup vs baseline: 1.3792x; 1.3792x over previous
#include <cuda_runtime.h>
#include <cuda_fp16.h>
#include <cstdint>

#define BATCH 32768

// ---------------- scratch (device globals; no allocations allowed) ----------
__device__ float g_qkv [(size_t)3 * BATCH * 1536];  // [s][b][1536] (q|k|v)
__device__ float g_P   [(size_t)3 * BATCH * 512];   // attention output, [s][b][512]
__device__ float g_attn[(size_t)3 * BATCH * 512];   // attn_out (post residual), [s][b][512]
__device__ float g_gate[(size_t)BATCH * 3];         // softmax gates
__device__ float g_h   [(size_t)BATCH * 1024];      // MLP hidden
__device__ float g_fus [(size_t)BATCH * 512];       // pre-LN fused

// ---------------- fp16 m16n8k16 MMA ------------------------------------------
__device__ __forceinline__ void mma16(float c[4], const uint32_t a[4], const uint32_t b[2]){
    asm volatile(
        "mma.sync.aligned.m16n8k16.row.col.f32.f16.f16.f32 "
        "{%0,%1,%2,%3}, {%4,%5,%6,%7}, {%8,%9}, {%0,%1,%2,%3};\n"
        : "+f"(c[0]), "+f"(c[1]), "+f"(c[2]), "+f"(c[3])
        : "r"(a[0]), "r"(a[1]), "r"(a[2]), "r"(a[3]),
          "r"(b[0]), "r"(b[1]));
}

// ---------------- generic 128x128x16 fp16 GEMM:  C = A * W^T (+epilogue) -----
// MODE 0: QKV       A = stream z (x0/x1/x2), K=512,  N=1536 -> g_qkv[z]
// MODE 1: out-proj  A = g_P (M=3B rows),     K=512,  N=512  -> g_attn (+bias+residual)
// MODE 2: MLP1      A = g_attn * gates,      K=1536, N=1024 -> g_h (SiLU(+bias))
// MODE 3: MLP2      A = g_h,                 K=1024, N=512  -> g_fus (+bias)
template<int MODE>
__global__ void __launch_bounds__(256)
gemm_kernel(const float* __restrict__ Wt, const float* __restrict__ bias,
            const float* __restrict__ x0, const float* __restrict__ x1,
            const float* __restrict__ x2)
{
    constexpr int KK = (MODE==0) ? 512  : (MODE==1) ? 512 : (MODE==2) ? 1536 : 1024;
    constexpr int KT = KK / 16;

    // half2 tiles: 128 rows x 8 half2 (16 halves) used, stride 12 for bank-freedom
    __shared__ __half2 sA[2][128][12];
    __shared__ __half2 sW[2][128][12];

    const int t    = threadIdx.x;
    const int lane = t & 31, warp = t >> 5;
    const int wm   = warp & 1;        // 2 warps along M (64 rows each)
    const int wn   = warp >> 1;       // 4 warps along N (32 cols each)
    const int gid  = lane >> 2, tig = lane & 3;

    const long long rowBase = (long long)blockIdx.y * 128;
    const int       colBase = blockIdx.x * 128;

    const int ldRow = t >> 2;         // 0..63
    const int ldCol = (t & 3) << 2;   // 0,4,8,12 (float granularity)

    const float* Aptr = nullptr;
    if constexpr (MODE==0) Aptr = (blockIdx.z==0) ? x0 : (blockIdx.z==1) ? x1 : x2;
    if constexpr (MODE==1) Aptr = g_P;
    if constexpr (MODE==3) Aptr = g_h;

    float acc[4][4][4];
    #pragma unroll
    for (int i=0;i<4;i++)
        #pragma unroll
        for (int j=0;j<4;j++)
            #pragma unroll
            for (int l=0;l<4;l++) acc[i][j][l] = 0.f;

    float4 pa0, pa1, pw0, pw1;

    auto gload = [&](int k0){
        if constexpr (MODE==2){
            const int c = k0 + ldCol;
            const int s = c >> 9, cc = c & 511;
            const long long r0 = rowBase + ldRow, r1 = r0 + 64;
            const float gs0 = g_gate[r0*3 + s];
            const float gs1 = g_gate[r1*3 + s];
            float4 a = *(const float4*)(g_attn + ((long long)s*BATCH + r0)*512 + cc);
            float4 b = *(const float4*)(g_attn + ((long long)s*BATCH + r1)*512 + cc);
            a.x*=gs0; a.y*=gs0; a.z*=gs0; a.w*=gs0;
            b.x*=gs1; b.y*=gs1; b.z*=gs1; b.w*=gs1;
            pa0 = a; pa1 = b;
        } else {
            pa0 = *(const float4*)(Aptr + (rowBase + ldRow     )*KK + k0 + ldCol);
            pa1 = *(const float4*)(Aptr + (rowBase + ldRow + 64)*KK + k0 + ldCol);
        }
        pw0 = *(const float4*)(Wt + (long long)(colBase + ldRow     )*KK + k0 + ldCol);
        pw1 = *(const float4*)(Wt + (long long)(colBase + ldRow + 64)*KK + k0 + ldCol);
    };
    auto cvt2 = [](float4 v) -> uint2 {
        __half2 lo = __floats2half2_rn(v.x, v.y);
        __half2 hi = __floats2half2_rn(v.z, v.w);
        uint2 r;
        r.x = *(uint32_t*)&lo;
        r.y = *(uint32_t*)&hi;
        return r;
    };
    auto sstore = [&](int buf){
        const int c2 = ldCol >> 1;   // half2 index: 0,2,4,6
        *(uint2*)&sA[buf][ldRow   ][c2] = cvt2(pa0);
        *(uint2*)&sA[buf][ldRow+64][c2] = cvt2(pa1);
        *(uint2*)&sW[buf][ldRow   ][c2] = cvt2(pw0);
        *(uint2*)&sW[buf][ldRow+64][c2] = cvt2(pw1);
    };

    gload(0);
    sstore(0);
    __syncthreads();

    int buf = 0;
    for (int kt = 0; kt < KT; kt++){
        if (kt + 1 < KT) gload((kt+1)*16);
        {
            // fragment loads (k-tile of 16 = one m16n8k16 step)
            uint32_t a[4][4];
            #pragma unroll
            for (int mi=0; mi<4; mi++){
                const int r = wm*64 + mi*16 + gid;
                a[mi][0] = *(const uint32_t*)&sA[buf][r  ][tig];
                a[mi][1] = *(const uint32_t*)&sA[buf][r+8][tig];
                a[mi][2] = *(const uint32_t*)&sA[buf][r  ][tig+4];
                a[mi][3] = *(const uint32_t*)&sA[buf][r+8][tig+4];
            }
            uint32_t b[4][2];
            #pragma unroll
            for (int ni=0; ni<4; ni++){
                const int cidx = wn*32 + ni*8 + gid;
                b[ni][0] = *(const uint32_t*)&sW[buf][cidx][tig];
                b[ni][1] = *(const uint32_t*)&sW[buf][cidx][tig+4];
            }
            #pragma unroll
            for (int mi=0; mi<4; mi++)
                #pragma unroll
                for (int ni=0; ni<4; ni++)
                    mma16(acc[mi][ni], a[mi], b[ni]);
        }
        if (kt + 1 < KT){
            sstore(buf ^ 1);
            __syncthreads();
            buf ^= 1;
        }
    }

    // epilogue (c layout: c0,c1 @ row gid cols 2*tig,2*tig+1; c2,c3 @ row gid+8)
    #pragma unroll
    for (int mi=0; mi<4; mi++){
        const long long gr0 = rowBase + wm*64 + mi*16 + gid;
        const long long gr1 = gr0 + 8;
        #pragma unroll
        for (int ni=0; ni<4; ni++){
            const int gc = colBase + wn*32 + ni*8 + (tig<<1);
            const float bi0 = bias[gc], bi1 = bias[gc+1];
            float v00 = acc[mi][ni][0] + bi0;
            float v01 = acc[mi][ni][1] + bi1;
            float v10 = acc[mi][ni][2] + bi0;
            float v11 = acc[mi][ni][3] + bi1;
            if constexpr (MODE==0){
                float* C = g_qkv + (long long)blockIdx.z * BATCH * 1536;
                *(float2*)&C[gr0*1536 + gc] = make_float2(v00, v01);
                *(float2*)&C[gr1*1536 + gc] = make_float2(v10, v11);
            } else if constexpr (MODE==1){
                const int s = (int)(rowBase >> 15);           // 32768 rows per stream block
                const float* xs = (s==0) ? x0 : (s==1) ? x1 : x2;
                const long long b0 = gr0 & 32767, b1 = gr1 & 32767;
                v00 += xs[b0*512 + gc]; v01 += xs[b0*512 + gc + 1];
                v10 += xs[b1*512 + gc]; v11 += xs[b1*512 + gc + 1];
                *(float2*)&g_attn[gr0*512 + gc] = make_float2(v00, v01);
                *(float2*)&g_attn[gr1*512 + gc] = make_float2(v10, v11);
            } else if constexpr (MODE==2){
                v00 = v00 / (1.f + expf(-v00));
                v01 = v01 / (1.f + expf(-v01));
                v10 = v10 / (1.f + expf(-v10));
                v11 = v11 / (1.f + expf(-v11));
                *(float2*)&g_h[gr0*1024 + gc] = make_float2(v00, v01);
                *(float2*)&g_h[gr1*1024 + gc] = make_float2(v10, v11);
            } else {
                *(float2*)&g_fus[gr0*512 + gc] = make_float2(v00, v01);
                *(float2*)&g_fus[gr1*512 + gc] = make_float2(v10, v11);
            }
        }
    }
}

// ---------------- attention over S=3 streams: warp per (b, head) -------------
__global__ void __launch_bounds__(256) attn_kernel(){
    const int gw   = (blockIdx.x * 256 + threadIdx.x) >> 5;   // B*H warps
    const int lane = threadIdx.x & 31;
    const int b = gw >> 3;
    const int h = gw & 7;
    float q[3][2], k[3][2], v[3][2];
    #pragma unroll
    for (int s=0; s<3; s++){
        const long long p = ((long long)s*BATCH + b)*1536 + h*64 + lane;
        q[s][0] = g_qkv[p];        q[s][1] = g_qkv[p+32];
        k[s][0] = g_qkv[p+512];    k[s][1] = g_qkv[p+544];
        v[s][0] = g_qkv[p+1024];   v[s][1] = g_qkv[p+1056];
    }
    float sc[3][3];
    #pragma unroll
    for (int i=0;i<3;i++)
        #pragma unroll
        for (int j=0;j<3;j++){
            float d = q[i][0]*k[j][0] + q[i][1]*k[j][1];
            #pragma unroll
            for (int o=16;o>0;o>>=1) d += __shfl_xor_sync(0xffffffffu, d, o);
            sc[i][j] = d * 0.125f;                 // 1/sqrt(64)
        }
    #pragma unroll
    for (int i=0;i<3;i++){
        const float m  = fmaxf(sc[i][0], fmaxf(sc[i][1], sc[i][2]));
        float e0 = expf(sc[i][0]-m), e1 = expf(sc[i][1]-m), e2 = expf(sc[i][2]-m);
        const float inv = 1.f/(e0+e1+e2);
        e0*=inv; e1*=inv; e2*=inv;
        const float o0 = e0*v[0][0] + e1*v[1][0] + e2*v[2][0];
        const float o1 = e0*v[0][1] + e1*v[1][1] + e2*v[2][1];
        const long long p = ((long long)i*BATCH + b)*512 + h*64 + lane;
        g_P[p]    = o0;
        g_P[p+32] = o1;
    }
}

// ---------------- gate: softmax(attn_out_flat @ w_gate^T + b_gate) -----------
__global__ void __launch_bounds__(256) gate_kernel(const float* __restrict__ w_gate,
                                                   const float* __restrict__ b_gate){
    __shared__ float wg[3*1536];
    for (int i = threadIdx.x; i < 3*1536; i += 256) wg[i] = w_gate[i];
    __syncthreads();
    const int warp = threadIdx.x >> 5, lane = threadIdx.x & 31;
    const long long b = (long long)blockIdx.x*8 + warp;
    float a0=0.f, a1=0.f, a2=0.f;
    for (int j = lane; j < 1536; j += 32){
        const int s = j >> 9, d = j & 511;
        const float v = g_attn[((long long)s*BATCH + b)*512 + d];
        a0 += v*wg[j]; a1 += v*wg[1536+j]; a2 += v*wg[3072+j];
    }
    #pragma unroll
    for (int o=16;o>0;o>>=1){
        a0 += __shfl_xor_sync(~0u,a0,o);
        a1 += __shfl_xor_sync(~0u,a1,o);
        a2 += __shfl_xor_sync(~0u,a2,o);
    }
    if (lane == 0){
        a0 += b_gate[0]; a1 += b_gate[1]; a2 += b_gate[2];
        const float m = fmaxf(a0, fmaxf(a1, a2));
        float e0 = expf(a0-m), e1 = expf(a1-m), e2 = expf(a2-m);
        const float inv = 1.f/(e0+e1+e2);
        g_gate[b*3+0] = e0*inv;
        g_gate[b*3+1] = e1*inv;
        g_gate[b*3+2] = e2*inv;
    }
}

// ---------------- LayerNorm: warp per row ------------------------------------
__global__ void __launch_bounds__(256) ln_kernel(const float* __restrict__ gamma,
                                                 const float* __restrict__ beta,
                                                 float* __restrict__ out){
    const int warp = threadIdx.x >> 5, lane = threadIdx.x & 31;
    const long long row = (long long)blockIdx.x*8 + warp;
    const float* src = g_fus + row*512;
    float4 vals[4];
    float sum = 0.f;
    #pragma unroll
    for (int i=0;i<4;i++){
        vals[i] = *(const float4*)(src + i*128 + lane*4);
        sum += vals[i].x + vals[i].y + vals[i].z + vals[i].w;
    }
    #pragma unroll
    for (int o=16;o>0;o>>=1) sum += __shfl_xor_sync(~0u,sum,o);
    const float mu = sum * (1.f/512.f);
    float ss = 0.f;
    #pragma unroll
    for (int i=0;i<4;i++){
        float dx;
        dx = vals[i].x-mu; ss += dx*dx;
        dx = vals[i].y-mu; ss += dx*dx;
        dx = vals[i].z-mu; ss += dx*dx;
        dx = vals[i].w-mu; ss += dx*dx;
    }
    #pragma unroll
    for (int o=16;o>0;o>>=1) ss += __shfl_xor_sync(~0u,ss,o);
    const float rstd = rsqrtf(ss*(1.f/512.f) + 1e-5f);
    #pragma unroll
    for (int i=0;i<4;i++){
        const int c = i*128 + lane*4;
        const float4 g  = *(const float4*)(gamma + c);
        const float4 bt = *(const float4*)(beta  + c);
        float4 o;
        o.x = (vals[i].x-mu)*rstd*g.x + bt.x;
        o.y = (vals[i].y-mu)*rstd*g.y + bt.y;
        o.z = (vals[i].z-mu)*rstd*g.z + bt.z;
        o.w = (vals[i].w-mu)*rstd*g.w + bt.w;
        *(float4*)(out + row*512 + c) = o;
    }
}

// ---------------- launch -----------------------------------------------------
extern "C" void kernel_launch(void* const* d_in, const int* in_sizes, int n_in,
                              void* d_out, int out_size){
    (void)in_sizes; (void)n_in; (void)out_size;
    const float* kin    = (const float*)d_in[0];
    const float* col    = (const float*)d_in[1];
    const float* spin   = (const float*)d_in[2];
    const float* w_in   = (const float*)d_in[3];
    const float* b_in   = (const float*)d_in[4];
    const float* w_out  = (const float*)d_in[5];
    const float* b_out  = (const float*)d_in[6];
    const float* w_gate = (const float*)d_in[7];
    const float* b_gate = (const float*)d_in[8];
    const float* w1     = (const float*)d_in[9];
    const float* b1     = (const float*)d_in[10];
    const float* w2     = (const float*)d_in[11];
    const float* b2     = (const float*)d_in[12];
    const float* gamma  = (const float*)d_in[13];
    const float* beta   = (const float*)d_in[14];
    float* out = (float*)d_out;

    dim3 blk(256);
    gemm_kernel<0><<<dim3(12, 256, 3), blk>>>(w_in,  b_in,  kin, col, spin); // QKV
    attn_kernel  <<<32768, blk>>>();                                          // S=3 attention
    gemm_kernel<1><<<dim3(4, 768),    blk>>>(w_out, b_out, kin, col, spin);  // out-proj + residual
    gate_kernel  <<<4096, blk>>>(w_gate, b_gate);                             // stream gates
    gemm_kernel<2><<<dim3(8, 256),    blk>>>(w1,    b1,    nullptr, nullptr, nullptr); // MLP1 + SiLU
    gemm_kernel<3><<<dim3(4, 256),    blk>>>(w2,    b2,    nullptr, nullptr, nullptr); // MLP2
    ln_kernel    <<<4096, blk>>>(gamma, beta, out);                           // LayerNorm
}

// round 9
// speedup vs baseline: 2.2326x; 1.6188x over previous
#include <cuda_runtime.h>
#include <cuda_fp16.h>
#include <cstdint>

#define BATCH 32768

// ---------------- scratch (device globals; no allocations allowed) ----------
__device__ __half h_in  [(size_t)3*BATCH*512];    // fp16 inputs [s][b][512]
__device__ __half h_win [1536*512];
__device__ __half h_wout[512*512];
__device__ __half h_w1  [1024*1536];
__device__ __half h_w2  [512*1024];
__device__ __half g_qkv [(size_t)3*BATCH*1536];   // [s][b][1536] (q|k|v)
__device__ __half g_P   [(size_t)3*BATCH*512];    // attention output
__device__ __half g_attn[(size_t)3*BATCH*512];    // attn_out (post residual)
__device__ __half g_ga  [(size_t)BATCH*1536];     // gated attn, [b][1536]
__device__ __half g_h   [(size_t)BATCH*1024];     // MLP hidden
__device__ float  g_fus [(size_t)BATCH*512];      // pre-LN fused (fp32)

// ---------------- helpers ----------------------------------------------------
__device__ __forceinline__ uint32_t smem_u32(const void* p){
    return (uint32_t)__cvta_generic_to_shared(p);
}
__device__ __forceinline__ void cp16(uint32_t dst, const void* src){
    asm volatile("cp.async.cg.shared.global [%0], [%1], 16;" :: "r"(dst), "l"(src));
}
__device__ __forceinline__ void ldsm4(uint32_t r[4], uint32_t addr){
    asm volatile("ldmatrix.sync.aligned.m8n8.x4.shared.b16 {%0,%1,%2,%3}, [%4];"
        : "=r"(r[0]), "=r"(r[1]), "=r"(r[2]), "=r"(r[3]) : "r"(addr));
}
__device__ __forceinline__ void mma16(float c[4], const uint32_t a[4], const uint32_t b[2]){
    asm volatile(
        "mma.sync.aligned.m16n8k16.row.col.f32.f16.f16.f32 "
        "{%0,%1,%2,%3}, {%4,%5,%6,%7}, {%8,%9}, {%0,%1,%2,%3};\n"
        : "+f"(c[0]), "+f"(c[1]), "+f"(c[2]), "+f"(c[3])
        : "r"(a[0]), "r"(a[1]), "r"(a[2]), "r"(a[3]), "r"(b[0]), "r"(b[1]));
}

// ---------------- fp32 -> fp16 conversion ------------------------------------
__global__ void cvt_kernel(const float* __restrict__ src, __half* __restrict__ dst, int n2){
    int i = blockIdx.x*blockDim.x + threadIdx.x;
    const int stride = gridDim.x*blockDim.x;
    for (; i < n2; i += stride){
        const float2 v = ((const float2*)src)[i];
        ((__half2*)dst)[i] = __floats2half2_rn(v.x, v.y);
    }
}

// ---------------- fp16 GEMM, cp.async 4-stage + ldmatrix ---------------------
// C[128x128 tile] = A[M][K](fp16) @ W[N][K]^T(fp16) + bias, epilogue per MODE.
// MODE 0: QKV      A=h_in (z-stream), K=512,  N=1536 -> g_qkv half
// MODE 1: out-proj A=g_P (3B rows),   K=512,  N=512  -> g_attn half (+residual fp32)
// MODE 2: MLP1     A=g_ga,            K=1536, N=1024 -> g_h half (SiLU)
// MODE 3: MLP2     A=g_h,             K=1024, N=512  -> g_fus fp32
template<int MODE>
__global__ void __launch_bounds__(256, 2)
gemm_kernel(const __half* __restrict__ A, const __half* __restrict__ W,
            const float* __restrict__ bias,
            const float* __restrict__ x0, const float* __restrict__ x1,
            const float* __restrict__ x2)
{
    constexpr int KK = (MODE==0) ? 512 : (MODE==1) ? 512 : (MODE==2) ? 1536 : 1024;
    constexpr int KT = KK / 16;

    // 4 stages x (A 4KB | W 4KB); rows of 32B (16 halves), swizzled 16B chunks
    __shared__ __align__(1024) char smem[4*8192];
    const uint32_t sb = smem_u32(smem);

    const int tid  = threadIdx.x;
    const int lane = tid & 31, warp = tid >> 5;
    const int wm   = warp & 1;        // 2 warps along M (64 rows)
    const int wn   = warp >> 1;       // 4 warps along N (32 cols)
    const int gid  = lane >> 2, tig = lane & 3;

    const long long rowBase = (long long)blockIdx.y * 128;
    const int       colBase = blockIdx.x * 128;

    const __half* Ab = A + ((MODE==0) ? (size_t)blockIdx.z*BATCH*512 : 0);

    // copy mapping: thread -> (row, 16B chunk)
    const int cprow = tid >> 1;       // 0..127
    const int cpc   = tid & 1;        // chunk 0/1
    const uint32_t cpdst = (uint32_t)(cprow*32 + ((cpc ^ ((cprow>>2)&1)) << 4));
    const __half* aSrc = Ab + (rowBase + cprow)*KK + cpc*8;
    const __half* wSrc = W  + (size_t)(colBase + cprow)*KK + cpc*8;

    // ldmatrix addresses (stage-relative)
    uint32_t aAddr[4], bAddr[2];
    {
        const int arl = lane & 15, ac = lane >> 4;
        #pragma unroll
        for (int mi = 0; mi < 4; mi++){
            const int r = wm*64 + mi*16 + arl;
            aAddr[mi] = (uint32_t)(r*32 + ((ac ^ ((r>>2)&1)) << 4));
        }
        const int brl = (lane & 7) + ((lane >> 4) << 3);
        const int bc  = (lane >> 3) & 1;
        #pragma unroll
        for (int p = 0; p < 2; p++){
            const int r = wn*32 + p*16 + brl;
            bAddr[p] = (uint32_t)(4096 + r*32 + ((bc ^ ((r>>2)&1)) << 4));
        }
    }

    float acc[4][4][4];
    #pragma unroll
    for (int i=0;i<4;i++)
        #pragma unroll
        for (int j=0;j<4;j++)
            #pragma unroll
            for (int l=0;l<4;l++) acc[i][j][l] = 0.f;

    auto issue = [&](int kt){
        const uint32_t d = sb + (kt & 3)*8192 + cpdst;
        cp16(d,        aSrc + kt*16);
        cp16(d + 4096, wSrc + kt*16);
    };

    issue(0); asm volatile("cp.async.commit_group;" ::: "memory");
    issue(1); asm volatile("cp.async.commit_group;" ::: "memory");
    issue(2); asm volatile("cp.async.commit_group;" ::: "memory");

    for (int kt = 0; kt < KT; kt++){
        asm volatile("cp.async.wait_group 2;" ::: "memory");
        __syncthreads();
        if (kt + 3 < KT) issue(kt + 3);
        asm volatile("cp.async.commit_group;" ::: "memory");

        const uint32_t st = sb + (kt & 3)*8192;
        uint32_t a[4][4], b[2][4];
        #pragma unroll
        for (int mi = 0; mi < 4; mi++) ldsm4(a[mi], st + aAddr[mi]);
        #pragma unroll
        for (int p = 0; p < 2; p++)    ldsm4(b[p],  st + bAddr[p]);

        #pragma unroll
        for (int mi = 0; mi < 4; mi++)
            #pragma unroll
            for (int ni = 0; ni < 4; ni++)
                mma16(acc[mi][ni], a[mi], &b[ni>>1][(ni&1)*2]);
    }

    // epilogue: acc[mi][ni] -> rows (gr0, gr0+8), cols (gc, gc+1)
    #pragma unroll
    for (int mi = 0; mi < 4; mi++){
        const long long gr0 = rowBase + wm*64 + mi*16 + gid;
        const long long gr1 = gr0 + 8;
        #pragma unroll
        for (int ni = 0; ni < 4; ni++){
            const int gc = colBase + wn*32 + ni*8 + (tig<<1);
            const float bi0 = bias[gc], bi1 = bias[gc+1];
            float v00 = acc[mi][ni][0] + bi0;
            float v01 = acc[mi][ni][1] + bi1;
            float v10 = acc[mi][ni][2] + bi0;
            float v11 = acc[mi][ni][3] + bi1;
            if constexpr (MODE==0){
                __half* C = g_qkv + (size_t)blockIdx.z*BATCH*1536;
                *(__half2*)&C[gr0*1536 + gc] = __floats2half2_rn(v00, v01);
                *(__half2*)&C[gr1*1536 + gc] = __floats2half2_rn(v10, v11);
            } else if constexpr (MODE==1){
                const int s = (int)(rowBase >> 15);
                const float* xs = (s==0) ? x0 : (s==1) ? x1 : x2;
                const long long b0 = gr0 & 32767, b1 = gr1 & 32767;
                v00 += xs[b0*512 + gc]; v01 += xs[b0*512 + gc + 1];
                v10 += xs[b1*512 + gc]; v11 += xs[b1*512 + gc + 1];
                *(__half2*)&g_attn[gr0*512 + gc] = __floats2half2_rn(v00, v01);
                *(__half2*)&g_attn[gr1*512 + gc] = __floats2half2_rn(v10, v11);
            } else if constexpr (MODE==2){
                v00 = v00 / (1.f + expf(-v00));
                v01 = v01 / (1.f + expf(-v01));
                v10 = v10 / (1.f + expf(-v10));
                v11 = v11 / (1.f + expf(-v11));
                *(__half2*)&g_h[gr0*1024 + gc] = __floats2half2_rn(v00, v01);
                *(__half2*)&g_h[gr1*1024 + gc] = __floats2half2_rn(v10, v11);
            } else {
                *(float2*)&g_fus[gr0*512 + gc] = make_float2(v00, v01);
                *(float2*)&g_fus[gr1*512 + gc] = make_float2(v10, v11);
            }
        }
    }
}

// ---------------- attention over S=3 streams: warp per (b, head) -------------
__global__ void __launch_bounds__(256) attn_kernel(){
    const int gw   = (blockIdx.x * 256 + threadIdx.x) >> 5;
    const int lane = threadIdx.x & 31;
    const int b = gw >> 3;
    const int h = gw & 7;
    float q[3][2], k[3][2], v[3][2];
    #pragma unroll
    for (int s=0; s<3; s++){
        const long long p = ((long long)s*BATCH + b)*1536 + h*64 + lane;
        q[s][0] = __half2float(g_qkv[p]);        q[s][1] = __half2float(g_qkv[p+32]);
        k[s][0] = __half2float(g_qkv[p+512]);    k[s][1] = __half2float(g_qkv[p+544]);
        v[s][0] = __half2float(g_qkv[p+1024]);   v[s][1] = __half2float(g_qkv[p+1056]);
    }
    float sc[3][3];
    #pragma unroll
    for (int i=0;i<3;i++)
        #pragma unroll
        for (int j=0;j<3;j++){
            float d = q[i][0]*k[j][0] + q[i][1]*k[j][1];
            #pragma unroll
            for (int o=16;o>0;o>>=1) d += __shfl_xor_sync(0xffffffffu, d, o);
            sc[i][j] = d * 0.125f;
        }
    #pragma unroll
    for (int i=0;i<3;i++){
        const float m  = fmaxf(sc[i][0], fmaxf(sc[i][1], sc[i][2]));
        float e0 = expf(sc[i][0]-m), e1 = expf(sc[i][1]-m), e2 = expf(sc[i][2]-m);
        const float inv = 1.f/(e0+e1+e2);
        e0*=inv; e1*=inv; e2*=inv;
        const float o0 = e0*v[0][0] + e1*v[1][0] + e2*v[2][0];
        const float o1 = e0*v[0][1] + e1*v[1][1] + e2*v[2][1];
        const long long p = ((long long)i*BATCH + b)*512 + h*64 + lane;
        g_P[p]    = __float2half(o0);
        g_P[p+32] = __float2half(o1);
    }
}

// ---------------- gate: softmax + apply, writes pre-gated g_ga ---------------
__global__ void __launch_bounds__(256) gate_kernel(const float* __restrict__ w_gate,
                                                   const float* __restrict__ b_gate){
    __shared__ float wg[3*1536];
    for (int i = threadIdx.x; i < 3*1536; i += 256) wg[i] = w_gate[i];
    __syncthreads();
    const int warp = threadIdx.x >> 5, lane = threadIdx.x & 31;
    const long long b = (long long)blockIdx.x*8 + warp;

    __half2 vals[3][8];
    float a0=0.f, a1=0.f, a2=0.f;
    #pragma unroll
    for (int s=0; s<3; s++){
        const __half2* src = (const __half2*)(g_attn + ((long long)s*BATCH + b)*512);
        #pragma unroll
        for (int i=0; i<8; i++){
            const int j2 = i*32 + lane;            // half2 index within 256
            const __half2 hv = src[j2];
            vals[s][i] = hv;
            const float2 f = __half22float2(hv);
            const int c = s*512 + j2*2;
            a0 += f.x*wg[c]        + f.y*wg[c+1];
            a1 += f.x*wg[1536+c]   + f.y*wg[1536+c+1];
            a2 += f.x*wg[3072+c]   + f.y*wg[3072+c+1];
        }
    }
    #pragma unroll
    for (int o=16;o>0;o>>=1){
        a0 += __shfl_xor_sync(~0u,a0,o);
        a1 += __shfl_xor_sync(~0u,a1,o);
        a2 += __shfl_xor_sync(~0u,a2,o);
    }
    a0 += b_gate[0]; a1 += b_gate[1]; a2 += b_gate[2];
    const float m = fmaxf(a0, fmaxf(a1, a2));
    float e0 = expf(a0-m), e1 = expf(a1-m), e2 = expf(a2-m);
    const float inv = 1.f/(e0+e1+e2);
    const float gf[3] = {e0*inv, e1*inv, e2*inv};

    __half2* dst = (__half2*)(g_ga + b*1536);
    #pragma unroll
    for (int s=0; s<3; s++){
        const __half2 g2 = __float2half2_rn(gf[s]);
        #pragma unroll
        for (int i=0; i<8; i++)
            dst[s*256 + i*32 + lane] = __hmul2(vals[s][i], g2);
    }
}

// ---------------- LayerNorm: warp per row ------------------------------------
__global__ void __launch_bounds__(256) ln_kernel(const float* __restrict__ gamma,
                                                 const float* __restrict__ beta,
                                                 float* __restrict__ out){
    const int warp = threadIdx.x >> 5, lane = threadIdx.x & 31;
    const long long row = (long long)blockIdx.x*8 + warp;
    const float* src = g_fus + row*512;
    float4 vals[4];
    float sum = 0.f;
    #pragma unroll
    for (int i=0;i<4;i++){
        vals[i] = *(const float4*)(src + i*128 + lane*4);
        sum += vals[i].x + vals[i].y + vals[i].z + vals[i].w;
    }
    #pragma unroll
    for (int o=16;o>0;o>>=1) sum += __shfl_xor_sync(~0u,sum,o);
    const float mu = sum * (1.f/512.f);
    float ss = 0.f;
    #pragma unroll
    for (int i=0;i<4;i++){
        float dx;
        dx = vals[i].x-mu; ss += dx*dx;
        dx = vals[i].y-mu; ss += dx*dx;
        dx = vals[i].z-mu; ss += dx*dx;
        dx = vals[i].w-mu; ss += dx*dx;
    }
    #pragma unroll
    for (int o=16;o>0;o>>=1) ss += __shfl_xor_sync(~0u,ss,o);
    const float rstd = rsqrtf(ss*(1.f/512.f) + 1e-5f);
    #pragma unroll
    for (int i=0;i<4;i++){
        const int c = i*128 + lane*4;
        const float4 g  = *(const float4*)(gamma + c);
        const float4 bt = *(const float4*)(beta  + c);
        float4 o;
        o.x = (vals[i].x-mu)*rstd*g.x + bt.x;
        o.y = (vals[i].y-mu)*rstd*g.y + bt.y;
        o.z = (vals[i].z-mu)*rstd*g.z + bt.z;
        o.w = (vals[i].w-mu)*rstd*g.w + bt.w;
        *(float4*)(out + row*512 + c) = o;
    }
}

// ---------------- launch -----------------------------------------------------
extern "C" void kernel_launch(void* const* d_in, const int* in_sizes, int n_in,
                              void* d_out, int out_size){
    (void)in_sizes; (void)n_in; (void)out_size;
    const float* kin    = (const float*)d_in[0];
    const float* col    = (const float*)d_in[1];
    const float* spin   = (const float*)d_in[2];
    const float* w_in   = (const float*)d_in[3];
    const float* b_in   = (const float*)d_in[4];
    const float* w_out  = (const float*)d_in[5];
    const float* b_out  = (const float*)d_in[6];
    const float* w_gate = (const float*)d_in[7];
    const float* b_gate = (const float*)d_in[8];
    const float* w1     = (const float*)d_in[9];
    const float* b1     = (const float*)d_in[10];
    const float* w2     = (const float*)d_in[11];
    const float* b2     = (const float*)d_in[12];
    const float* gamma  = (const float*)d_in[13];
    const float* beta   = (const float*)d_in[14];
    float* out = (float*)d_out;

    __half *p_in, *p_win, *p_wout, *p_w1, *p_w2, *p_P, *p_ga, *p_h, *p_qkv;
    cudaGetSymbolAddress((void**)&p_in,  h_in);
    cudaGetSymbolAddress((void**)&p_win, h_win);
    cudaGetSymbolAddress((void**)&p_wout,h_wout);
    cudaGetSymbolAddress((void**)&p_w1,  h_w1);
    cudaGetSymbolAddress((void**)&p_w2,  h_w2);
    cudaGetSymbolAddress((void**)&p_P,   g_P);
    cudaGetSymbolAddress((void**)&p_ga,  g_ga);
    cudaGetSymbolAddress((void**)&p_h,   g_h);
    cudaGetSymbolAddress((void**)&p_qkv, g_qkv);

    dim3 blk(256);
    const size_t SD = (size_t)BATCH*512;
    // fp32 -> fp16 conversions
    cvt_kernel<<<2048, blk>>>(kin,  p_in,            (int)(SD/2));
    cvt_kernel<<<2048, blk>>>(col,  p_in +   SD,     (int)(SD/2));
    cvt_kernel<<<2048, blk>>>(spin, p_in + 2*SD,     (int)(SD/2));
    cvt_kernel<<<512,  blk>>>(w_in,  p_win,  1536*512/2);
    cvt_kernel<<<512,  blk>>>(w_out, p_wout, 512*512/2);
    cvt_kernel<<<512,  blk>>>(w1,    p_w1,   1024*1536/2);
    cvt_kernel<<<512,  blk>>>(w2,    p_w2,   512*1024/2);

    gemm_kernel<0><<<dim3(12, 256, 3), blk>>>(p_in, p_win,  b_in,  nullptr, nullptr, nullptr);
    attn_kernel  <<<32768, blk>>>();
    gemm_kernel<1><<<dim3(4, 768),    blk>>>(p_P,  p_wout, b_out, kin, col, spin);
    gate_kernel  <<<4096, blk>>>(w_gate, b_gate);
    gemm_kernel<2><<<dim3(8, 256),    blk>>>(p_ga, p_w1,   b1,    nullptr, nullptr, nullptr);
    gemm_kernel<3><<<dim3(4, 256),    blk>>>(p_h,  p_w2,   b2,    nullptr, nullptr, nullptr);
    ln_kernel    <<<4096, blk>>>(gamma, beta, out);
}